// round 8
// baseline (speedup 1.0000x reference)
#include <cuda_runtime.h>

// MHSA_fl_bs — analytic collapse, 2 launches.
//
// softmax over the HEAD axis of head-broadcast-identical scores == 1/16
// exactly => q, k, Wq, bq, Wk, bk are dead.
//   vsum[b,d]  = sum_q v[b,q,d]
//   s[b,d']    = dot(vsum[b,:], Wv[d',:]) + Sq*bv[d']
//   o[b,d]     = bb[d] + (1/16) * dot(s[b,:], Wb[d,:])
//   out[k,b,d] = o[b,d]            (broadcast over all Sk)
// B=4, Sq=Sk=1024, D=1024, dh=64, H=16. Cost = 16MB read + 16MB write.
//
// Launch 1 (k_fused): 256 CTAs reduce v into g_vsum via REDG; the LAST CTA
// to finish (done-counter) computes s and o alone and restores the replay
// invariants (g_vsum == 0, g_done == 0). No spin -> deadlock-free.
// Launch 2 (k_bcast): 16 MB coalesced broadcast write.

#define BB     4
#define SQ     1024
#define SK     1024
#define DD     1024
#define DH     64
#define HINV   (1.0f / 16.0f)
#define NCTA   (BB * (SQ / 16))     // 256 CTAs in k_fused

__device__ float    g_vsum[BB * DD];   // ==0 at every kernel_launch entry
__device__ float    g_o[BB * DD];
__device__ unsigned g_done;            // ==0 at every kernel_launch entry

// ---------------------------------------------------------------------------
__global__ void __launch_bounds__(1024)
k_fused(const float4* __restrict__ v,
        const float*  __restrict__ Wv, const float* __restrict__ bv,
        const float*  __restrict__ Wb, const float* __restrict__ bb_) {
    const int b    = blockIdx.x;          // 0..3
    const int qc   = blockIdx.y;          // 0..63 : 16-row chunk
    const int qsub = threadIdx.x >> 8;    // 0..3
    const int d4   = threadIdx.x & 255;   // 0..255
    const int tid  = threadIdx.x;

    // ---- phase 1: reduce 16 q-rows, REDG-accumulate into g_vsum ----
    {
        const float4* base =
            v + ((size_t)b * SQ + (size_t)qc * 16 + qsub) * (DD / 4) + d4;
        float4 acc = make_float4(0.f, 0.f, 0.f, 0.f);
#pragma unroll
        for (int i = 0; i < 4; ++i) {     // rows qsub, qsub+4, qsub+8, qsub+12
            float4 x = base[(size_t)i * 4 * (DD / 4)];
            acc.x += x.x; acc.y += x.y; acc.z += x.z; acc.w += x.w;
        }
        float* dst = g_vsum + b * DD + d4 * 4;
        atomicAdd(dst + 0, acc.x);
        atomicAdd(dst + 1, acc.y);
        atomicAdd(dst + 2, acc.z);
        atomicAdd(dst + 3, acc.w);
    }

    // ---- last-CTA handoff ----
    __threadfence();
    __syncthreads();
    __shared__ unsigned isLast;
    if (tid == 0)
        isLast = (atomicAdd(&g_done, 1u) == NCTA - 1u) ? 1u : 0u;
    __syncthreads();
    if (!isLast) return;

    // ---- tail (one CTA, 1024 threads): s then o ----
    __shared__ float vs[BB * DD];     // 16 KB
    __shared__ float s_sm[BB * DH];   // 1 KB

    __threadfence();                  // see all CTAs' REDG results
#pragma unroll
    for (int i = 0; i < 4; ++i)       // g_vsum -> smem (L2-hot, coalesced)
        vs[tid + i * 1024] = g_vsum[tid + i * 1024];
    __syncthreads();

    // s[b,dp] = dot(vs[b,:], Wv[dp,:]) + Sq*bv[dp]; 4 lanes per (b,dp)
    {
        const int quarter = tid & 3;        // 0..3 : 256-elem slice
        const int pair    = tid >> 2;       // 0..255
        const int sb      = pair >> 6;      // batch
        const int dp      = pair & 63;

        const float4* wrow = (const float4*)(Wv + (size_t)dp * DD) + quarter * 64;
        const float*  x    = vs + sb * DD + quarter * 256;
        float acc = 0.0f;
#pragma unroll 16
        for (int i = 0; i < 64; ++i) {
            float4 w = wrow[i];
            acc += w.x * x[4 * i] + w.y * x[4 * i + 1] +
                   w.z * x[4 * i + 2] + w.w * x[4 * i + 3];
        }
        acc += __shfl_down_sync(0xFFFFFFFFu, acc, 2, 4);
        acc += __shfl_down_sync(0xFFFFFFFFu, acc, 1, 4);
        if (quarter == 0) s_sm[pair] = acc + (float)SQ * bv[dp];
    }
    __syncthreads();

    // o[b,d] = bb[d] + (1/16)*dot(s[b,:], Wb[d,:]); 4 outputs per thread
#pragma unroll
    for (int i = 0; i < 4; ++i) {
        const int idx = tid + i * 1024;
        const int ob  = idx >> 10;
        const int d   = idx & 1023;
        const float4* wrow = (const float4*)(Wb + (size_t)d * DH);
        const float*  s    = s_sm + ob * DH;
        float acc = 0.0f;
#pragma unroll
        for (int j = 0; j < DH / 4; ++j) {
            float4 w = wrow[j];
            acc += w.x * s[4 * j] + w.y * s[4 * j + 1] +
                   w.z * s[4 * j + 2] + w.w * s[4 * j + 3];
        }
        g_o[idx] = acc * HINV + bb_[d];
    }

    // ---- restore replay invariants ----
    ((float4*)g_vsum)[tid] = make_float4(0.f, 0.f, 0.f, 0.f);
    if (tid == 0) g_done = 0u;
}

// ---------------------------------------------------------------------------
// Broadcast o[b,:] across all Sk. out layout [Sk, B, D]. Each thread holds
// one float4 of g_o in a register and stores it to KREP consecutive k
// positions. Pure coalesced 16 MB write; g_o is L2-resident.
#define KREP 4
__global__ void k_bcast(float4* __restrict__ out) {
    const int i   = blockIdx.x * blockDim.x + threadIdx.x;
    const int row = i >> 8;          // (k_base, b); 256 float4 per (k,b) row
    const int d4  = i & 255;
    const int b   = row & 3;
    const int k0  = (row >> 2) * KREP;

    const float4 val = ((const float4*)g_o)[b * 256 + d4];
    float4* dst = out + (((size_t)k0 * BB + b) << 8) + d4;
#pragma unroll
    for (int r = 0; r < KREP; ++r)
        dst[(size_t)r * BB * (DD / 4)] = val;
}

// ---------------------------------------------------------------------------
extern "C" void kernel_launch(void* const* d_in, const int* in_sizes, int n_in,
                              void* d_out, int out_size) {
    // metadata order: q, k, h, w, v, Wq, bq, Wk, bk, Wv, bv, Wb, bb
    const float* v  = (const float*)d_in[4];
    const float* Wv = (const float*)d_in[9];
    const float* bv = (const float*)d_in[10];
    const float* Wb = (const float*)d_in[11];
    const float* bb = (const float*)d_in[12];

    dim3 g1(BB, SQ / 16);
    k_fused<<<g1, 1024>>>((const float4*)v, Wv, bv, Wb, bb);

    k_bcast<<<(SK / KREP) * BB * (DD / 4) / 256, 256>>>((float4*)d_out);
}

// round 9
// speedup vs baseline: 4.3817x; 4.3817x over previous
#include <cuda_runtime.h>

// MHSA_fl_bs — analytic collapse, atomic-free, 5 launches.
//
// softmax over the HEAD axis of head-broadcast-identical scores == 1/16
// exactly => q, k, Wq, bq, Wk, bk are dead.
//   vsum[b,d]  = sum_q v[b,q,d]
//   s[b,d']    = dot(vsum[b,:], Wv[d',:]) + Sq*bv[d']
//   o[b,d]     = bb[d] + (1/16) * dot(s[b,:], Wb[d,:])
//   out[k,b,d] = o[b,d]            (broadcast over all Sk)
// B=4, Sq=Sk=1024, D=1024, dh=64, H=16. Cost = 16MB read + 16MB write.
//
// R8 lesson: global FP atomics with 256 ops/address serialized at L2 and
// cost ~70us. This version has ZERO atomics: tree reduction via plain
// stores. All scratch buffers are fully overwritten before being read on
// every call -> no cross-replay invariants.

#define BB     4
#define SQ     1024
#define SK     1024
#define DD     1024
#define DH     64
#define HINV   (1.0f / 16.0f)
#define NQC    64                     // partial chunks per batch (16 rows each)

__device__ float g_part[BB * NQC * DD];  // 1 MB partial rows
__device__ float g_vsum[BB * DD];        // 16 KB
__device__ float g_s[BB * DH];           // 1 KB
__device__ float g_o[BB * DD];           // 16 KB

// ---------------------------------------------------------------------------
// Stage 1: grid (BB, 64) = 256 CTAs x 1024 threads. Thread (qsub = tid>>8,
// d4 = tid&255) reduces 4 q-rows (4 independent LDG.128); warp-local smem
// combine of the 4 qsubs; qsub==0 threads store the partial row with plain
// STG.128. Pure coalesced 16 MB read + 1 MB write. No atomics.
__global__ void __launch_bounds__(1024)
k_part(const float4* __restrict__ v) {
    __shared__ float4 buf[3][256];        // qsub 1..3 park here

    const int b    = blockIdx.x;
    const int qc   = blockIdx.y;          // 16-row chunk
    const int qsub = threadIdx.x >> 8;    // 0..3
    const int d4   = threadIdx.x & 255;   // 0..255

    const float4* base =
        v + ((size_t)b * SQ + (size_t)qc * 16 + qsub) * (DD / 4) + d4;

    float4 acc = make_float4(0.f, 0.f, 0.f, 0.f);
#pragma unroll
    for (int i = 0; i < 4; ++i) {         // rows qsub, qsub+4, qsub+8, qsub+12
        float4 x = base[(size_t)i * 4 * (DD / 4)];
        acc.x += x.x; acc.y += x.y; acc.z += x.z; acc.w += x.w;
    }
    if (qsub) buf[qsub - 1][d4] = acc;
    __syncthreads();

    if (qsub == 0) {
        float4 p = buf[0][d4], q = buf[1][d4], r = buf[2][d4];
        acc.x += p.x + q.x + r.x;
        acc.y += p.y + q.y + r.y;
        acc.z += p.z + q.z + r.z;
        acc.w += p.w + q.w + r.w;
        ((float4*)g_part)[((size_t)b * NQC + qc) * (DD / 4) + d4] = acc;
    }
}

// ---------------------------------------------------------------------------
// Stage 2: grid 16 (= BB*4) x 256 threads. Each CTA reduces the 64 partial
// rows for 256 d-columns of one batch. 64 KB L2-hot read per CTA, fully
// coalesced (stride DD), deep unroll -> high MLP.
__global__ void k_red() {
    const int b    = blockIdx.x >> 2;
    const int dblk = blockIdx.x & 3;
    const int d    = dblk * 256 + threadIdx.x;

    const float* p = g_part + (size_t)b * NQC * DD + d;
    float acc = 0.0f;
#pragma unroll 16
    for (int qc = 0; qc < NQC; ++qc)
        acc += p[(size_t)qc * DD];
    g_vsum[b * DD + d] = acc;
}

// ---------------------------------------------------------------------------
// Stage 3: grid 256 (= BB*DH) x 128 threads. One dot per CTA:
// s[b,dp] = dot(vsum[b,:], Wv[dp,:]) + Sq*bv[dp].
__global__ void k_s(const float* __restrict__ Wv, const float* __restrict__ bv) {
    __shared__ float red[4];
    const int b  = blockIdx.x >> 6;
    const int dp = blockIdx.x & 63;
    const int t  = threadIdx.x;

    const float4* wrow = (const float4*)(Wv + (size_t)dp * DD);
    const float4* vs   = (const float4*)(g_vsum + b * DD);

    float acc = 0.0f;
#pragma unroll
    for (int j = 0; j < 2; ++j) {
        int i = t + j * 128;
        float4 w = wrow[i], x = vs[i];
        acc += w.x * x.x + w.y * x.y + w.z * x.z + w.w * x.w;
    }
#pragma unroll
    for (int off = 16; off > 0; off >>= 1)
        acc += __shfl_down_sync(0xFFFFFFFFu, acc, off);
    if ((t & 31) == 0) red[t >> 5] = acc;
    __syncthreads();
    if (t == 0)
        g_s[b * DH + dp] = red[0] + red[1] + red[2] + red[3] + (float)SQ * bv[dp];
}

// ---------------------------------------------------------------------------
// Stage 4: grid 32 (= BB*8) x 128 threads. Each CTA computes 128 outputs:
// o[b,d] = bb[d] + (1/16)*dot(s[b,:], Wb[d,:]).
__global__ void k_o(const float* __restrict__ Wb, const float* __restrict__ bb_) {
    __shared__ float s[DH];
    const int b    = blockIdx.x >> 3;
    const int dblk = blockIdx.x & 7;
    const int d    = dblk * 128 + threadIdx.x;

    if (threadIdx.x < DH) s[threadIdx.x] = g_s[b * DH + threadIdx.x];
    __syncthreads();

    const float4* wrow = (const float4*)(Wb + (size_t)d * DH);
    float acc = 0.0f;
#pragma unroll
    for (int i = 0; i < DH / 4; ++i) {
        float4 w = wrow[i];
        acc += w.x * s[4 * i] + w.y * s[4 * i + 1] +
               w.z * s[4 * i + 2] + w.w * s[4 * i + 3];
    }
    g_o[b * DD + d] = acc * HINV + bb_[d];
}

// ---------------------------------------------------------------------------
// Stage 5: broadcast o[b,:] across all Sk. out layout [Sk, B, D].
// 256 CTAs x 256 threads; each thread performs ONE L2 load of its float4
// of g_o, then 16 independent STG.128 (consecutive k, stride B*D). R8
// showed this kernel is issue/latency-bound, not DRAM-bound (output fits
// in L2) -> maximize stores per load and store ILP.
#define KREP 16
__global__ void k_bcast(float4* __restrict__ out) {
    const int c   = blockIdx.x;          // 0..255
    const int d4  = threadIdx.x;         // 0..255
    const int b   = c & 3;
    const int k0  = (c >> 2) * KREP;     // 64 k-chunks of 16

    const float4 val = ((const float4*)g_o)[b * 256 + d4];
    float4* dst = out + (((size_t)k0 * BB + b) << 8) + d4;
#pragma unroll
    for (int r = 0; r < KREP; ++r)
        dst[(size_t)r * BB * (DD / 4)] = val;
}

// ---------------------------------------------------------------------------
extern "C" void kernel_launch(void* const* d_in, const int* in_sizes, int n_in,
                              void* d_out, int out_size) {
    // metadata order: q, k, h, w, v, Wq, bq, Wk, bk, Wv, bv, Wb, bb
    const float* v  = (const float*)d_in[4];
    const float* Wv = (const float*)d_in[9];
    const float* bv = (const float*)d_in[10];
    const float* Wb = (const float*)d_in[11];
    const float* bb = (const float*)d_in[12];

    dim3 g1(BB, NQC);
    k_part<<<g1, 1024>>>((const float4*)v);

    k_red<<<BB * 4, 256>>>();
    k_s<<<BB * DH, 128>>>(Wv, bv);
    k_o<<<BB * 8, 128>>>(Wb, bb);

    k_bcast<<<SK / KREP * BB, 256>>>((float4*)d_out);
}